// round 6
// baseline (speedup 1.0000x reference)
#include <cuda_runtime.h>
#include <cuda_bf16.h>
#include <math.h>
#include <cstdint>

// ---------------- problem constants ----------------
// x:      [512, 1, 28, 28]
// conv_w: [256, 1, 9, 9]   conv_b: [256]
// y:      [512, 256, 20, 20]
// prim_w: [256 oc][256 ic][9][9], stride 2 -> p: [512, 256, 6, 6]
// u:      [512, 1152, 8]   (r = m*36 + oh*6 + ow, i = oc>>5, m = oc&31)
// route_w:[10, 1152, 8, 16]
// out:    [512, 10]

#define NB 512

// ---------------- scratch ----------------
__device__ float    g_y[(size_t)NB * 256 * 400];        // 210 MB
__device__ float    g_u[(size_t)NB * 1152 * 8];         // 18.9 MB
__device__ uint32_t g_wbf[(size_t)2 * 256 * 128 * 52];  // 13.1 MB [half][ic][ocl][52 bf16x2]
__device__ float    g_logits[NB * 10];

// ---------------- cp.async helpers (generic PTX, sm_80+) ----------------
__device__ __forceinline__ uint32_t smem_u32(const void* p) {
    uint32_t a;
    asm("{ .reg .u64 t; cvta.to.shared.u64 t, %1; cvt.u32.u64 %0, t; }"
        : "=r"(a) : "l"(p));
    return a;
}
__device__ __forceinline__ void cp16(uint32_t dst, const void* src) {
    asm volatile("cp.async.ca.shared.global [%0], [%1], 16;"
                 :: "r"(dst), "l"(src) : "memory");
}
#define CP_COMMIT() asm volatile("cp.async.commit_group;" ::: "memory")
#define CP_WAIT1()  asm volatile("cp.async.wait_group 1;" ::: "memory")

// ======================================================================
// weight prep: prim_w -> bf16x2 pairs, taps 81..103 zero
// ======================================================================
__global__ void prep_w_kernel(const float* __restrict__ pw) {
    size_t idx = (size_t)blockIdx.x * 256 + threadIdx.x;
    const size_t total = (size_t)2 * 256 * 128 * 52;
    if (idx >= total) return;
    int p = (int)(idx % 52);
    size_t r = idx / 52;
    int ocl = (int)(r % 128);
    size_t r2 = r / 128;
    int ic = (int)(r2 % 256);
    int half = (int)(r2 / 256);
    int k0 = 2 * p, k1 = 2 * p + 1;
    const float* src = pw + ((size_t)(half * 128 + ocl)) * 20736 + ic * 81;
    float v0 = (k0 < 81) ? src[k0] : 0.f;
    float v1 = (k1 < 81) ? src[k1] : 0.f;
    __nv_bfloat162 h = __floats2bfloat162_rn(v0, v1);
    g_wbf[idx] = *(uint32_t*)&h;
}

// ======================================================================
// conv1: block = (oh, b), 256 threads = oc
// ======================================================================
__global__ void conv1_kernel(const float* __restrict__ x,
                             const float* __restrict__ w,
                             const float* __restrict__ bias) {
    extern __shared__ float sm1[];
    float* sw = sm1;
    float* sx = sm1 + 20736;
    int oh = blockIdx.x, b = blockIdx.y, t = threadIdx.x;

    for (int i = t; i < 20736; i += 256) sw[i] = w[i];
    if (t < 252) sx[t] = x[(size_t)b * 784 + oh * 28 + t];
    __syncthreads();

    int oc = t;
    float acc[20];
    float bv = bias[oc];
#pragma unroll
    for (int i = 0; i < 20; i++) acc[i] = bv;

    const float* wp = sw + oc * 81;
#pragma unroll
    for (int kh = 0; kh < 9; kh++) {
        float rin[28];
#pragma unroll
        for (int j = 0; j < 28; j++) rin[j] = sx[kh * 28 + j];
#pragma unroll
        for (int kw = 0; kw < 9; kw++) {
            float wv = wp[kh * 9 + kw];
#pragma unroll
            for (int ow = 0; ow < 20; ow++) acc[ow] += wv * rin[kw + ow];
        }
    }
    float* yp = g_y + ((size_t)(b * 256 + oc)) * 400 + oh * 20;
#pragma unroll
    for (int ow = 0; ow < 20; ow++) yp[ow] = acc[ow];
}

// ======================================================================
// conv2 via mma.sync bf16 m16n8k16, cp.async double-buffered pipeline.
// Block: 128 oc x 72 px (2 images). 256 thr = warps 4(M) x 2(N).
// Warp tile 32 oc x 40 px. K = 256 ic x 96 taps (81 real, rows 52 words).
// smem: A[2][6656]w + B[4160]w + y[2][800]f = 76.3 KB -> 2 CTA/SM.
// Pipeline: prefetch(ic+1) -> wait(ic) -> build B -> mma, dist-1.
// ======================================================================
#define C2_AW 6656
#define C2_BW 4160
#define C2_YW 800
#define C2_SMEM ((2 * C2_AW + C2_BW + 2 * C2_YW) * 4)

template <int KG>
__device__ __forceinline__ void emit_b(uint32_t* dst, const float* ys) {
#pragma unroll
    for (int i = 0; i < 16; i++) {
        int k0 = 32 * KG + 2 * i;
        int k1 = k0 + 1;
        if (k0 >= 81) break;   // tail pairs permanently zero (pre-zeroed)
        float v0 = ys[(k0 / 9) * 20 + (k0 % 9)];
        float v1 = (k1 < 81) ? ys[(k1 / 9) * 20 + (k1 % 9)] : 0.f;
        __nv_bfloat162 h = __floats2bfloat162_rn(v0, v1);
        dst[i] = *(uint32_t*)&h;
    }
}

__global__ void __launch_bounds__(256, 2) conv2_mma_kernel(
        const float* __restrict__ pb) {
    extern __shared__ float sm[];
    uint32_t* aSm = (uint32_t*)sm;                  // 2 x 6656 words
    uint32_t* bSm = (uint32_t*)sm + 2 * C2_AW;      // 4160 words
    float*    ySm = sm + 2 * C2_AW + C2_BW;         // 2 x 800 floats

    uint32_t aAddr = smem_u32(aSm);
    uint32_t yAddr = smem_u32(ySm);

    int t = threadIdx.x, lane = t & 31, wid = t >> 5;
    int gid = lane >> 2, tig = lane & 3;
    int wm = wid >> 1, wn = wid & 1;
    int half = blockIdx.x;
    int b0 = blockIdx.y * 2;

    // zero B once (pad rows 72..79, words >= 41 within k-groups, words 48..51)
    for (int i = t; i < C2_BW; i += 256) bSm[i] = 0u;

    // B-gather geometry (ic-invariant): 240 threads = 80 n x 3 k-groups
    int gn = -1, kg = 0, ybofs = 0;
    if (t < 240) {
        int n = t % 80;
        kg = t / 80;
        if (n < 72) {
            int img = n >= 36;
            int pix = n - 36 * img;
            int oh = pix / 6, ow = pix - oh * 6;
            gn = n;
            ybofs = img * 400 + 40 * oh + 2 * ow;
        }
    }

    float acc[2][5][4];
#pragma unroll
    for (int mt = 0; mt < 2; mt++)
#pragma unroll
        for (int j = 0; j < 5; j++)
#pragma unroll
            for (int k = 0; k < 4; k++) acc[mt][j][k] = 0.f;

    const uint32_t* wsrc = g_wbf + (size_t)half * 256 * C2_AW;
    const float* ysrc0 = g_y + (size_t)b0 * 256 * 400;
    const float* ysrc1 = g_y + (size_t)(b0 + 1) * 256 * 400;

    // ---- prefetch lambda-equivalent (macro-ish inline) ----
    // A: 1664 16B chunks; y: 200 16B chunks (100 per image)
#define PREFETCH(ic_, bi_) do {                                                \
        uint32_t aD = aAddr + (bi_) * (C2_AW * 4);                             \
        const uint32_t* aS = wsrc + (size_t)(ic_) * C2_AW;                     \
        for (int i = t; i < 1664; i += 256)                                    \
            cp16(aD + i * 16, aS + i * 4);                                     \
        uint32_t yD = yAddr + (bi_) * (C2_YW * 4);                             \
        if (t < 200) {                                                         \
            const float* yS = (t < 100) ? (ysrc0 + (size_t)(ic_) * 400 + t * 4)\
                                        : (ysrc1 + (size_t)(ic_) * 400 + (t - 100) * 4); \
            cp16(yD + t * 16, yS);                                             \
        }                                                                      \
    } while (0)

    PREFETCH(0, 0);
    CP_COMMIT();

    for (int ic = 0; ic < 256; ic++) {
        int cur = ic & 1, nxt = cur ^ 1;
        if (ic + 1 < 256) PREFETCH(ic + 1, nxt);
        CP_COMMIT();
        CP_WAIT1();
        __syncthreads();   // buf[cur] resident+visible; prev iter fully done

        // build B from y[cur]
        if (gn >= 0) {
            uint32_t* dst = bSm + gn * 52 + kg * 16;
            const float* ys = ySm + cur * C2_YW + ybofs;
            if (kg == 0)      emit_b<0>(dst, ys);
            else if (kg == 1) emit_b<1>(dst, ys);
            else              emit_b<2>(dst, ys);
        }
        __syncthreads();   // B ready

        const uint32_t* aCur = aSm + cur * C2_AW;
#pragma unroll
        for (int s = 0; s < 6; s++) {
            int kc = s * 8 + tig;
            uint32_t a[2][4];
#pragma unroll
            for (int mt = 0; mt < 2; mt++) {
                const uint32_t* ap = aCur + (wm * 32 + mt * 16 + gid) * 52 + kc;
                a[mt][0] = ap[0];
                a[mt][1] = ap[8 * 52];
                a[mt][2] = ap[4];
                a[mt][3] = ap[8 * 52 + 4];
            }
#pragma unroll
            for (int j = 0; j < 5; j++) {
                const uint32_t* bp = bSm + (wn * 40 + j * 8 + gid) * 52 + kc;
                uint32_t br0 = bp[0];
                uint32_t br1 = bp[4];
#pragma unroll
                for (int mt = 0; mt < 2; mt++) {
                    asm volatile(
                        "mma.sync.aligned.m16n8k16.row.col.f32.bf16.bf16.f32 "
                        "{%0,%1,%2,%3},{%4,%5,%6,%7},{%8,%9},{%0,%1,%2,%3};"
                        : "+f"(acc[mt][j][0]), "+f"(acc[mt][j][1]),
                          "+f"(acc[mt][j][2]), "+f"(acc[mt][j][3])
                        : "r"(a[mt][0]), "r"(a[mt][1]), "r"(a[mt][2]),
                          "r"(a[mt][3]), "r"(br0), "r"(br1));
                }
            }
        }
        __syncthreads();   // mma reads done; buf[cur] free for next prefetch
    }
#undef PREFETCH

    // epilogue: D[oc][n] -> g_u[b][r][i] + bias
    int ocb = half * 128;
#pragma unroll
    for (int mt = 0; mt < 2; mt++) {
        int row0 = wm * 32 + mt * 16 + gid;
#pragma unroll
        for (int h2 = 0; h2 < 2; h2++) {
            int oc = ocb + row0 + h2 * 8;
            float bv = pb[oc];
            int i8 = oc >> 5, m = oc & 31;
#pragma unroll
            for (int j = 0; j < 5; j++) {
#pragma unroll
                for (int cc = 0; cc < 2; cc++) {
                    int n = wn * 40 + j * 8 + 2 * tig + cc;
                    if (n < 72) {
                        int img = n >= 36;
                        int pix = n - 36 * img;
                        g_u[((size_t)(b0 + img)) * 9216 + (m * 36 + pix) * 8 + i8] =
                            acc[mt][j][h2 * 2 + cc] + bv;
                    }
                }
            }
        }
    }
}

// ======================================================================
// squash u over the 8-dim capsule axis (in place)
// ======================================================================
__global__ void squash_kernel() {
    int idx = blockIdx.x * blockDim.x + threadIdx.x;
    if (idx >= NB * 1152) return;
    float* p = g_u + (size_t)idx * 8;
    float4 a = *(float4*)p, b = *(float4*)(p + 4);
    float sn = a.x*a.x + a.y*a.y + a.z*a.z + a.w*a.w
             + b.x*b.x + b.y*b.y + b.z*b.z + b.w*b.w;
    float sc = sqrtf(sn) / (1.f + sn);
    a.x *= sc; a.y *= sc; a.z *= sc; a.w *= sc;
    b.x *= sc; b.y *= sc; b.z *= sc; b.w *= sc;
    *(float4*)p = a; *(float4*)(p + 4) = b;
}

// ======================================================================
// Fused priors + 3 routing iterations. Block = (c, b), 512 threads.
// ======================================================================
__global__ void route_kernel(const float* __restrict__ rw) {
    extern __shared__ float sm2[];
    float* spri  = sm2;               // 18432
    float* su    = sm2 + 18432;       // 9216
    float* sblog = su + 9216;         // 1152
    float* sred  = sblog + 1152;      // 256
    float* sv    = sred + 256;        // 16
    float* sscr  = sv + 16;           // 40
    int c = blockIdx.x, b = blockIdx.y, t = threadIdx.x;
    int lane = t & 31, warp = t >> 5;   // 16 warps

    {
        const float4* ug = (const float4*)(g_u + (size_t)b * 9216);
        float4* su4 = (float4*)su;
        for (int i = t; i < 2304; i += 512) su4[i] = ug[i];
        for (int r = t; r < 1152; r += 512) sblog[r] = 0.f;
    }
    __syncthreads();

    {
        int o4 = (t & 3) * 4, rb = t >> 2;
        for (int j = 0; j < 9; j++) {
            int r = rb + 128 * j;
            const float* wr = rw + ((size_t)c * 1152 + r) * 128 + o4;
            const float* ur = su + r * 8;
            float ax = 0.f, ay = 0.f, az = 0.f, aw = 0.f;
#pragma unroll
            for (int i = 0; i < 8; i++) {
                float uv = ur[i];
                float4 w = *(const float4*)(wr + i * 16);
                ax += uv * w.x; ay += uv * w.y; az += uv * w.z; aw += uv * w.w;
            }
            float4 o; o.x = ax; o.y = ay; o.z = az; o.w = aw;
            *(float4*)(spri + r * 16 + o4) = o;
        }
    }
    __syncthreads();

    float snv = 0.f;
    for (int iter = 0; iter < 3; iter++) {
        float lm = -1e30f;
        for (int r = t; r < 1152; r += 512) lm = fmaxf(lm, sblog[r]);
#pragma unroll
        for (int off = 16; off; off >>= 1)
            lm = fmaxf(lm, __shfl_xor_sync(0xffffffffu, lm, off));
        if (lane == 0) sscr[warp] = lm;
        __syncthreads();
        float bmax = sscr[0];
#pragma unroll
        for (int wn = 1; wn < 16; wn++) bmax = fmaxf(bmax, sscr[wn]);
        float ls = 0.f;
        for (int r = t; r < 1152; r += 512) ls += expf(sblog[r] - bmax);
#pragma unroll
        for (int off = 16; off; off >>= 1)
            ls += __shfl_xor_sync(0xffffffffu, ls, off);
        if (lane == 0) sscr[16 + warp] = ls;
        __syncthreads();
        float bsum = 0.f;
#pragma unroll
        for (int wn = 0; wn < 16; wn++) bsum += sscr[16 + wn];
        float inv = 1.f / bsum;

        float sa[16];
#pragma unroll
        for (int o = 0; o < 16; o++) sa[o] = 0.f;
        for (int r = t; r < 1152; r += 512) {
            float pr = expf(sblog[r] - bmax) * inv;
            const float* pp = spri + r * 16;
#pragma unroll
            for (int o = 0; o < 16; o++) sa[o] += pp[o] * pr;
        }
#pragma unroll
        for (int o = 0; o < 16; o++) {
#pragma unroll
            for (int off = 16; off; off >>= 1)
                sa[o] += __shfl_xor_sync(0xffffffffu, sa[o], off);
        }
        if (lane == 0) {
#pragma unroll
            for (int o = 0; o < 16; o++) sred[warp * 16 + o] = sa[o];
        }
        __syncthreads();
        if (t < 32) {
            float sval = 0.f;
            if (t < 16) {
#pragma unroll
                for (int wn = 0; wn < 16; wn++) sval += sred[wn * 16 + t];
            }
            float sn = sval * sval;
#pragma unroll
            for (int off = 16; off; off >>= 1)
                sn += __shfl_xor_sync(0xffffffffu, sn, off);
            float sc = sqrtf(sn) / (1.f + sn);
            if (t < 16) sv[t] = sval * sc;
            if (t == 0) sscr[32] = sn;
        }
        __syncthreads();
        snv = sscr[32];

        if (iter < 2) {
            for (int r = t; r < 1152; r += 512) {
                const float* pp = spri + r * 16;
                float d = 0.f;
#pragma unroll
                for (int o = 0; o < 16; o++) d += pp[o] * sv[o];
                sblog[r] += d;
            }
            __syncthreads();
        }
    }
    if (t == 0) g_logits[b * 10 + c] = snv / (1.f + snv);
}

// ======================================================================
__global__ void softmax_kernel(float* __restrict__ out) {
    int b = blockIdx.x * blockDim.x + threadIdx.x;
    if (b >= NB) return;
    float l[10];
#pragma unroll
    for (int i = 0; i < 10; i++) l[i] = g_logits[b * 10 + i];
    float m = l[0];
#pragma unroll
    for (int i = 1; i < 10; i++) m = fmaxf(m, l[i]);
    float s = 0.f;
#pragma unroll
    for (int i = 0; i < 10; i++) { l[i] = expf(l[i] - m); s += l[i]; }
    float inv = 1.f / s;
#pragma unroll
    for (int i = 0; i < 10; i++) out[b * 10 + i] = l[i] * inv;
}

// ======================================================================
extern "C" void kernel_launch(void* const* d_in, const int* in_sizes, int n_in,
                              void* d_out, int out_size) {
    const float* x  = (const float*)d_in[0];
    const float* cw = (const float*)d_in[1];
    const float* cb = (const float*)d_in[2];
    const float* pw = (const float*)d_in[3];
    const float* pb = (const float*)d_in[4];
    const float* rw = (const float*)d_in[5];
    float* out = (float*)d_out;

    const int c1_smem = (20736 + 252) * 4;
    const int rt_smem = (18432 + 9216 + 1152 + 256 + 16 + 40) * 4;
    cudaFuncSetAttribute(conv1_kernel,
        cudaFuncAttributeMaxDynamicSharedMemorySize, c1_smem);
    cudaFuncSetAttribute(conv2_mma_kernel,
        cudaFuncAttributeMaxDynamicSharedMemorySize, C2_SMEM);
    cudaFuncSetAttribute(route_kernel,
        cudaFuncAttributeMaxDynamicSharedMemorySize, rt_smem);

    prep_w_kernel<<<(int)(((size_t)2 * 256 * 128 * 52 + 255) / 256), 256>>>(pw);
    conv1_kernel<<<dim3(20, NB), 256, c1_smem>>>(x, cw, cb);
    conv2_mma_kernel<<<dim3(2, NB / 2), 256, C2_SMEM>>>(pb);
    squash_kernel<<<(NB * 1152 + 255) / 256, 256>>>();
    route_kernel<<<dim3(10, NB), 512, rt_smem>>>(rw);
    softmax_kernel<<<(NB + 255) / 256, 256>>>(out);
}

// round 7
// speedup vs baseline: 1.1403x; 1.1403x over previous
#include <cuda_runtime.h>
#include <cuda_bf16.h>
#include <math.h>
#include <cstdint>

// ---------------- problem constants ----------------
// x:      [512, 1, 28, 28]
// conv_w: [256, 1, 9, 9]   conv_b: [256]
// y:      [512, 256, 20, 20]
// prim_w: [256 oc][256 ic][9][9], stride 2 -> p: [512, 256, 6, 6]
// u:      [512, 1152, 8]   (r = m*36 + oh*6 + ow, i = oc>>5, m = oc&31)
// route_w:[10, 1152, 8, 16]
// out:    [512, 10]

#define NB 512

// ---------------- scratch ----------------
__device__ float    g_y[(size_t)NB * 256 * 400];        // 210 MB
__device__ float    g_u[(size_t)NB * 1152 * 8];         // 18.9 MB
__device__ uint32_t g_wbf[(size_t)2 * 256 * 128 * 52];  // 13.1 MB [half][ic][ocl][52 bf16x2]
__device__ float    g_logits[NB * 10];

// ---------------- cp.async helpers (generic PTX, sm_80+) ----------------
__device__ __forceinline__ uint32_t smem_u32(const void* p) {
    uint32_t a;
    asm("{ .reg .u64 t; cvta.to.shared.u64 t, %1; cvt.u32.u64 %0, t; }"
        : "=r"(a) : "l"(p));
    return a;
}
__device__ __forceinline__ void cp16(uint32_t dst, const void* src) {
    asm volatile("cp.async.ca.shared.global [%0], [%1], 16;"
                 :: "r"(dst), "l"(src) : "memory");
}
#define CP_COMMIT() asm volatile("cp.async.commit_group;" ::: "memory")
#define CP_WAIT1()  asm volatile("cp.async.wait_group 1;" ::: "memory")

// ======================================================================
// weight prep: prim_w -> bf16x2 pairs, taps 81..103 zero
// ======================================================================
__global__ void prep_w_kernel(const float* __restrict__ pw) {
    size_t idx = (size_t)blockIdx.x * 256 + threadIdx.x;
    const size_t total = (size_t)2 * 256 * 128 * 52;
    if (idx >= total) return;
    int p = (int)(idx % 52);
    size_t r = idx / 52;
    int ocl = (int)(r % 128);
    size_t r2 = r / 128;
    int ic = (int)(r2 % 256);
    int half = (int)(r2 / 256);
    int k0 = 2 * p, k1 = 2 * p + 1;
    const float* src = pw + ((size_t)(half * 128 + ocl)) * 20736 + ic * 81;
    float v0 = (k0 < 81) ? src[k0] : 0.f;
    float v1 = (k1 < 81) ? src[k1] : 0.f;
    __nv_bfloat162 h = __floats2bfloat162_rn(v0, v1);
    g_wbf[idx] = *(uint32_t*)&h;
}

// ======================================================================
// conv1: block = (oh, b), 256 threads = oc
// ======================================================================
__global__ void conv1_kernel(const float* __restrict__ x,
                             const float* __restrict__ w,
                             const float* __restrict__ bias) {
    extern __shared__ float sm1[];
    float* sw = sm1;
    float* sx = sm1 + 20736;
    int oh = blockIdx.x, b = blockIdx.y, t = threadIdx.x;

    for (int i = t; i < 20736; i += 256) sw[i] = w[i];
    if (t < 252) sx[t] = x[(size_t)b * 784 + oh * 28 + t];
    __syncthreads();

    int oc = t;
    float acc[20];
    float bv = bias[oc];
#pragma unroll
    for (int i = 0; i < 20; i++) acc[i] = bv;

    const float* wp = sw + oc * 81;
#pragma unroll
    for (int kh = 0; kh < 9; kh++) {
        float rin[28];
#pragma unroll
        for (int j = 0; j < 28; j++) rin[j] = sx[kh * 28 + j];
#pragma unroll
        for (int kw = 0; kw < 9; kw++) {
            float wv = wp[kh * 9 + kw];
#pragma unroll
            for (int ow = 0; ow < 20; ow++) acc[ow] += wv * rin[kw + ow];
        }
    }
    float* yp = g_y + ((size_t)(b * 256 + oc)) * 400 + oh * 20;
#pragma unroll
    for (int ow = 0; ow < 20; ow++) yp[ow] = acc[ow];
}

// ======================================================================
// conv2 via mma.sync bf16 m16n8k16, cp.async double-buffered pipeline.
// Block: 128 oc x 144 px (4 images, padded to 160). 256 thr = 4(M)x2(N) warps.
// Warp tile 32 oc x 80 px. K = 256 ic x 96 taps (81 real, rows 52 words).
// smem: A[2][6656]w + B[8320]w + y[2][1600]f = 97 KB -> 2 CTA/SM.
// Grid = 2 x 128 = 256 CTAs = ONE wave at 2 CTA/SM.
// ======================================================================
#define C2_AW 6656
#define C2_BW 8320
#define C2_YW 1600
#define C2_SMEM ((2 * C2_AW + C2_BW + 2 * C2_YW) * 4)

template <int KG>
__device__ __forceinline__ void emit_b(uint32_t* dst, const float* ys) {
#pragma unroll
    for (int i = 0; i < 16; i++) {
        int k0 = 32 * KG + 2 * i;
        int k1 = k0 + 1;
        if (k0 >= 81) break;   // tail pairs permanently zero (pre-zeroed)
        float v0 = ys[(k0 / 9) * 20 + (k0 % 9)];
        float v1 = (k1 < 81) ? ys[(k1 / 9) * 20 + (k1 % 9)] : 0.f;
        __nv_bfloat162 h = __floats2bfloat162_rn(v0, v1);
        dst[i] = *(uint32_t*)&h;
    }
}

__global__ void __launch_bounds__(256, 2) conv2_mma_kernel(
        const float* __restrict__ pb) {
    extern __shared__ float sm[];
    uint32_t* aSm = (uint32_t*)sm;                  // 2 x 6656 words
    uint32_t* bSm = (uint32_t*)sm + 2 * C2_AW;      // 8320 words
    float*    ySm = sm + 2 * C2_AW + C2_BW;         // 2 x 1600 floats

    uint32_t aAddr = smem_u32(aSm);
    uint32_t yAddr = smem_u32(ySm);

    int t = threadIdx.x, lane = t & 31, wid = t >> 5;
    int gid = lane >> 2, tig = lane & 3;
    int wm = wid >> 1, wn = wid & 1;
    int half = blockIdx.x;
    int b0 = blockIdx.y * 4;

    // zero B once (pad rows 144..159 and word tails stay zero forever)
    for (int i = t; i < C2_BW; i += 256) bSm[i] = 0u;

    // B-gather geometry (ic-invariant): 480 units = 160 n x 3 k-groups,
    // each thread owns units t and t+256.
    int gn[2], gkg[2], gyofs[2];
#pragma unroll
    for (int s = 0; s < 2; s++) {
        int u = t + s * 256;
        gn[s] = -1;
        if (u < 480) {
            int n = u % 160, kg = u / 160;
            if (n < 144) {
                int img = n / 36, pix = n % 36;
                int oh = pix / 6, ow = pix - oh * 6;
                gn[s] = n; gkg[s] = kg;
                gyofs[s] = img * 400 + 40 * oh + 2 * ow;
            }
        }
    }

    float acc[2][10][4];
#pragma unroll
    for (int mt = 0; mt < 2; mt++)
#pragma unroll
        for (int j = 0; j < 10; j++)
#pragma unroll
            for (int k = 0; k < 4; k++) acc[mt][j][k] = 0.f;

    const uint32_t* wsrc = g_wbf + (size_t)half * 256 * C2_AW;
    const float* ysrc = g_y + (size_t)b0 * 256 * 400;

    // A: 1664 16B chunks; y: 4 images x 100 chunks mapped on a 128 grid
#define PREFETCH(ic_, bi_) do {                                                \
        uint32_t aD = aAddr + (bi_) * (C2_AW * 4);                             \
        const uint32_t* aS = wsrc + (size_t)(ic_) * C2_AW;                     \
        for (int i = t; i < 1664; i += 256)                                    \
            cp16(aD + i * 16, aS + i * 4);                                     \
        uint32_t yD = yAddr + (bi_) * (C2_YW * 4);                             \
        for (int i = t; i < 512; i += 256) {                                   \
            int im = i >> 7, off = i & 127;                                    \
            if (off < 100)                                                     \
                cp16(yD + (im * 400 + off * 4) * 4,                            \
                     ysrc + ((size_t)im * 256 + (ic_)) * 400 + off * 4);       \
        }                                                                      \
    } while (0)

    PREFETCH(0, 0);
    CP_COMMIT();

    for (int ic = 0; ic < 256; ic++) {
        int cur = ic & 1, nxt = cur ^ 1;
        if (ic + 1 < 256) PREFETCH(ic + 1, nxt);
        CP_COMMIT();
        CP_WAIT1();
        __syncthreads();   // buf[cur] resident+visible; prev mma done

        // build B from y[cur]
#pragma unroll
        for (int s = 0; s < 2; s++) {
            if (gn[s] >= 0) {
                uint32_t* dst = bSm + gn[s] * 52 + gkg[s] * 16;
                const float* ys = ySm + cur * C2_YW + gyofs[s];
                if (gkg[s] == 0)      emit_b<0>(dst, ys);
                else if (gkg[s] == 1) emit_b<1>(dst, ys);
                else                  emit_b<2>(dst, ys);
            }
        }
        __syncthreads();   // B ready

        const uint32_t* aCur = aSm + cur * C2_AW;
#pragma unroll
        for (int s = 0; s < 6; s++) {
            int kc = s * 8 + tig;
            uint32_t a[2][4];
#pragma unroll
            for (int mt = 0; mt < 2; mt++) {
                const uint32_t* ap = aCur + (wm * 32 + mt * 16 + gid) * 52 + kc;
                a[mt][0] = ap[0];
                a[mt][1] = ap[8 * 52];
                a[mt][2] = ap[4];
                a[mt][3] = ap[8 * 52 + 4];
            }
#pragma unroll
            for (int j = 0; j < 10; j++) {
                const uint32_t* bp = bSm + (wn * 80 + j * 8 + gid) * 52 + kc;
                uint32_t br0 = bp[0];
                uint32_t br1 = bp[4];
#pragma unroll
                for (int mt = 0; mt < 2; mt++) {
                    asm volatile(
                        "mma.sync.aligned.m16n8k16.row.col.f32.bf16.bf16.f32 "
                        "{%0,%1,%2,%3},{%4,%5,%6,%7},{%8,%9},{%0,%1,%2,%3};"
                        : "+f"(acc[mt][j][0]), "+f"(acc[mt][j][1]),
                          "+f"(acc[mt][j][2]), "+f"(acc[mt][j][3])
                        : "r"(a[mt][0]), "r"(a[mt][1]), "r"(a[mt][2]),
                          "r"(a[mt][3]), "r"(br0), "r"(br1));
                }
            }
        }
        __syncthreads();   // mma reads done; buf[cur] free for next prefetch
    }
#undef PREFETCH

    // epilogue: D[oc][n] -> g_u[b][r][i] + bias
    int ocb = half * 128;
#pragma unroll
    for (int mt = 0; mt < 2; mt++) {
        int row0 = wm * 32 + mt * 16 + gid;
#pragma unroll
        for (int h2 = 0; h2 < 2; h2++) {
            int oc = ocb + row0 + h2 * 8;
            float bv = pb[oc];
            int i8 = oc >> 5, m = oc & 31;
#pragma unroll
            for (int j = 0; j < 10; j++) {
#pragma unroll
                for (int cc = 0; cc < 2; cc++) {
                    int n = wn * 80 + j * 8 + 2 * tig + cc;
                    if (n < 144) {
                        int img = n / 36, pix = n - 36 * img;
                        g_u[((size_t)(b0 + img)) * 9216 + (m * 36 + pix) * 8 + i8] =
                            acc[mt][j][h2 * 2 + cc] + bv;
                    }
                }
            }
        }
    }
}

// ======================================================================
// squash u over the 8-dim capsule axis (in place)
// ======================================================================
__global__ void squash_kernel() {
    int idx = blockIdx.x * blockDim.x + threadIdx.x;
    if (idx >= NB * 1152) return;
    float* p = g_u + (size_t)idx * 8;
    float4 a = *(float4*)p, b = *(float4*)(p + 4);
    float sn = a.x*a.x + a.y*a.y + a.z*a.z + a.w*a.w
             + b.x*b.x + b.y*b.y + b.z*b.z + b.w*b.w;
    float sc = sqrtf(sn) / (1.f + sn);
    a.x *= sc; a.y *= sc; a.z *= sc; a.w *= sc;
    b.x *= sc; b.y *= sc; b.z *= sc; b.w *= sc;
    *(float4*)p = a; *(float4*)(p + 4) = b;
}

// ======================================================================
// Fused priors + 3 routing iterations. Block = (c, b), 512 threads.
// u read straight from gmem in priors stage (each row read once).
// smem 79.6 KB -> 2 CTA/SM.
// ======================================================================
__global__ void __launch_bounds__(512, 2) route_kernel(const float* __restrict__ rw) {
    extern __shared__ float sm2[];
    float* spri  = sm2;               // 18432
    float* sblog = sm2 + 18432;       // 1152
    float* sred  = sblog + 1152;      // 256
    float* sv    = sred + 256;        // 16
    float* sscr  = sv + 16;           // 40
    int c = blockIdx.x, b = blockIdx.y, t = threadIdx.x;
    int lane = t & 31, warp = t >> 5;   // 16 warps

    for (int r = t; r < 1152; r += 512) sblog[r] = 0.f;

    // priors[r][o] = sum_i u[r][i] * route_w[c][r][i][o]; u straight from gmem
    {
        int o4 = (t & 3) * 4, rb = t >> 2;
        const float* ub = g_u + (size_t)b * 9216;
        for (int j = 0; j < 9; j++) {
            int r = rb + 128 * j;
            const float* wr = rw + ((size_t)c * 1152 + r) * 128 + o4;
            const float4* ur = (const float4*)(ub + r * 8);
            float4 u0 = ur[0], u1 = ur[1];
            float uu[8] = {u0.x, u0.y, u0.z, u0.w, u1.x, u1.y, u1.z, u1.w};
            float ax = 0.f, ay = 0.f, az = 0.f, aw = 0.f;
#pragma unroll
            for (int i = 0; i < 8; i++) {
                float uv = uu[i];
                float4 w = *(const float4*)(wr + i * 16);
                ax += uv * w.x; ay += uv * w.y; az += uv * w.z; aw += uv * w.w;
            }
            float4 o; o.x = ax; o.y = ay; o.z = az; o.w = aw;
            *(float4*)(spri + r * 16 + o4) = o;
        }
    }
    __syncthreads();

    float snv = 0.f;
    for (int iter = 0; iter < 3; iter++) {
        float lm = -1e30f;
        for (int r = t; r < 1152; r += 512) lm = fmaxf(lm, sblog[r]);
#pragma unroll
        for (int off = 16; off; off >>= 1)
            lm = fmaxf(lm, __shfl_xor_sync(0xffffffffu, lm, off));
        if (lane == 0) sscr[warp] = lm;
        __syncthreads();
        float bmax = sscr[0];
#pragma unroll
        for (int wn = 1; wn < 16; wn++) bmax = fmaxf(bmax, sscr[wn]);
        float ls = 0.f;
        for (int r = t; r < 1152; r += 512) ls += expf(sblog[r] - bmax);
#pragma unroll
        for (int off = 16; off; off >>= 1)
            ls += __shfl_xor_sync(0xffffffffu, ls, off);
        if (lane == 0) sscr[16 + warp] = ls;
        __syncthreads();
        float bsum = 0.f;
#pragma unroll
        for (int wn = 0; wn < 16; wn++) bsum += sscr[16 + wn];
        float inv = 1.f / bsum;

        float sa[16];
#pragma unroll
        for (int o = 0; o < 16; o++) sa[o] = 0.f;
        for (int r = t; r < 1152; r += 512) {
            float pr = expf(sblog[r] - bmax) * inv;
            const float* pp = spri + r * 16;
#pragma unroll
            for (int o = 0; o < 16; o++) sa[o] += pp[o] * pr;
        }
#pragma unroll
        for (int o = 0; o < 16; o++) {
#pragma unroll
            for (int off = 16; off; off >>= 1)
                sa[o] += __shfl_xor_sync(0xffffffffu, sa[o], off);
        }
        if (lane == 0) {
#pragma unroll
            for (int o = 0; o < 16; o++) sred[warp * 16 + o] = sa[o];
        }
        __syncthreads();
        if (t < 32) {
            float sval = 0.f;
            if (t < 16) {
#pragma unroll
                for (int wn = 0; wn < 16; wn++) sval += sred[wn * 16 + t];
            }
            float sn = sval * sval;
#pragma unroll
            for (int off = 16; off; off >>= 1)
                sn += __shfl_xor_sync(0xffffffffu, sn, off);
            float sc = sqrtf(sn) / (1.f + sn);
            if (t < 16) sv[t] = sval * sc;
            if (t == 0) sscr[32] = sn;
        }
        __syncthreads();
        snv = sscr[32];

        if (iter < 2) {
            for (int r = t; r < 1152; r += 512) {
                const float* pp = spri + r * 16;
                float d = 0.f;
#pragma unroll
                for (int o = 0; o < 16; o++) d += pp[o] * sv[o];
                sblog[r] += d;
            }
            __syncthreads();
        }
    }
    if (t == 0) g_logits[b * 10 + c] = snv / (1.f + snv);
}

// ======================================================================
__global__ void softmax_kernel(float* __restrict__ out) {
    int b = blockIdx.x * blockDim.x + threadIdx.x;
    if (b >= NB) return;
    float l[10];
#pragma unroll
    for (int i = 0; i < 10; i++) l[i] = g_logits[b * 10 + i];
    float m = l[0];
#pragma unroll
    for (int i = 1; i < 10; i++) m = fmaxf(m, l[i]);
    float s = 0.f;
#pragma unroll
    for (int i = 0; i < 10; i++) { l[i] = expf(l[i] - m); s += l[i]; }
    float inv = 1.f / s;
#pragma unroll
    for (int i = 0; i < 10; i++) out[b * 10 + i] = l[i] * inv;
}

// ======================================================================
extern "C" void kernel_launch(void* const* d_in, const int* in_sizes, int n_in,
                              void* d_out, int out_size) {
    const float* x  = (const float*)d_in[0];
    const float* cw = (const float*)d_in[1];
    const float* cb = (const float*)d_in[2];
    const float* pw = (const float*)d_in[3];
    const float* pb = (const float*)d_in[4];
    const float* rw = (const float*)d_in[5];
    float* out = (float*)d_out;

    const int c1_smem = (20736 + 252) * 4;
    const int rt_smem = (18432 + 1152 + 256 + 16 + 40) * 4;
    cudaFuncSetAttribute(conv1_kernel,
        cudaFuncAttributeMaxDynamicSharedMemorySize, c1_smem);
    cudaFuncSetAttribute(conv2_mma_kernel,
        cudaFuncAttributeMaxDynamicSharedMemorySize, C2_SMEM);
    cudaFuncSetAttribute(route_kernel,
        cudaFuncAttributeMaxDynamicSharedMemorySize, rt_smem);

    prep_w_kernel<<<(int)(((size_t)2 * 256 * 128 * 52 + 255) / 256), 256>>>(pw);
    conv1_kernel<<<dim3(20, NB), 256, c1_smem>>>(x, cw, cb);
    conv2_mma_kernel<<<dim3(2, NB / 4), 256, C2_SMEM>>>(pb);
    squash_kernel<<<(NB * 1152 + 255) / 256, 256>>>();
    route_kernel<<<dim3(10, NB), 512, rt_smem>>>(rw);
    softmax_kernel<<<(NB + 255) / 256, 256>>>(out);
}

// round 8
// speedup vs baseline: 1.1866x; 1.0406x over previous
#include <cuda_runtime.h>
#include <cuda_bf16.h>
#include <math.h>
#include <cstdint>

// ---------------- problem constants ----------------
// x:      [512, 1, 28, 28]
// conv_w: [256, 1, 9, 9]   conv_b: [256]
// y:      [512, 256, 20, 20]
// prim_w: [256 oc][256 ic][9][9], stride 2 -> p: [512, 256, 6, 6]
// u:      [512, 1152, 8]   (r = m*36 + oh*6 + ow, i = oc>>5, m = oc&31)
// route_w:[10, 1152, 8, 16]
// out:    [512, 10]

#define NB 512

// ---------------- scratch ----------------
__device__ float    g_y[(size_t)NB * 256 * 400];        // 210 MB
__device__ float    g_u[(size_t)NB * 1152 * 8];         // 18.9 MB
__device__ uint32_t g_wbf[(size_t)2 * 256 * 128 * 52];  // 13.1 MB [half][ic][ocl][52 bf16x2]
__device__ float    g_logits[NB * 10];

// ---------------- PTX helpers (generic, sm_80+) ----------------
__device__ __forceinline__ uint32_t smem_u32(const void* p) {
    uint32_t a;
    asm("{ .reg .u64 t; cvta.to.shared.u64 t, %1; cvt.u32.u64 %0, t; }"
        : "=r"(a) : "l"(p));
    return a;
}
__device__ __forceinline__ void cp16(uint32_t dst, const void* src) {
    asm volatile("cp.async.ca.shared.global [%0], [%1], 16;"
                 :: "r"(dst), "l"(src) : "memory");
}
#define CP_COMMIT() asm volatile("cp.async.commit_group;" ::: "memory")
#define CP_WAIT0()  asm volatile("cp.async.wait_group 0;" ::: "memory")

// ======================================================================
// weight prep: prim_w -> bf16x2 pairs, taps 81..103 zero
// ======================================================================
__global__ void prep_w_kernel(const float* __restrict__ pw) {
    size_t idx = (size_t)blockIdx.x * 256 + threadIdx.x;
    const size_t total = (size_t)2 * 256 * 128 * 52;
    if (idx >= total) return;
    int p = (int)(idx % 52);
    size_t r = idx / 52;
    int ocl = (int)(r % 128);
    size_t r2 = r / 128;
    int ic = (int)(r2 % 256);
    int half = (int)(r2 / 256);
    int k0 = 2 * p, k1 = 2 * p + 1;
    const float* src = pw + ((size_t)(half * 128 + ocl)) * 20736 + ic * 81;
    float v0 = (k0 < 81) ? src[k0] : 0.f;
    float v1 = (k1 < 81) ? src[k1] : 0.f;
    __nv_bfloat162 h = __floats2bfloat162_rn(v0, v1);
    g_wbf[idx] = *(uint32_t*)&h;
}

// ======================================================================
// conv1: block = (oh, b), 256 threads = oc
// ======================================================================
__global__ void conv1_kernel(const float* __restrict__ x,
                             const float* __restrict__ w,
                             const float* __restrict__ bias) {
    extern __shared__ float sm1[];
    float* sw = sm1;
    float* sx = sm1 + 20736;
    int oh = blockIdx.x, b = blockIdx.y, t = threadIdx.x;

    for (int i = t; i < 20736; i += 256) sw[i] = w[i];
    if (t < 252) sx[t] = x[(size_t)b * 784 + oh * 28 + t];
    __syncthreads();

    int oc = t;
    float acc[20];
    float bv = bias[oc];
#pragma unroll
    for (int i = 0; i < 20; i++) acc[i] = bv;

    const float* wp = sw + oc * 81;
#pragma unroll
    for (int kh = 0; kh < 9; kh++) {
        float rin[28];
#pragma unroll
        for (int j = 0; j < 28; j++) rin[j] = sx[kh * 28 + j];
#pragma unroll
        for (int kw = 0; kw < 9; kw++) {
            float wv = wp[kh * 9 + kw];
#pragma unroll
            for (int ow = 0; ow < 20; ow++) acc[ow] += wv * rin[kw + ow];
        }
    }
    float* yp = g_y + ((size_t)(b * 256 + oc)) * 400 + oh * 20;
#pragma unroll
    for (int ow = 0; ow < 20; ow++) yp[ow] = acc[ow];
}

// ======================================================================
// conv2 via mma.sync bf16 m16n8k16.
//   Block: 128 oc x 144 px (4 images, exact). 256 thr = 4(M) x 2(N) warps.
//   Warp tile 32 oc x 72 px (j=9). K = 256 ic x 96 words (81 real).
//   A: register fragments loaded DIRECTLY from g_wbf (L2), no smem.
//   B: double-buffered smem [2][144][52]w, built from y; build(ic+1)
//      overlaps mma(ic) -> ONE barrier per ic.
//   B frags via ldmatrix.x2 (row stride 52 words = conflict-free).
//   y: double-buffered via cp.async, distance 2.
//   smem: 2*7488w + 2*1600w = 72,704 B.
// ======================================================================
#define C2_BW 7488
#define C2_YW 1600
#define C2_SMEM ((2 * C2_BW + 2 * C2_YW) * 4)

template <int KG>
__device__ __forceinline__ void emit_b(uint32_t* dst, const float* ys) {
#pragma unroll
    for (int i = 0; i < 16; i++) {
        int k0 = 32 * KG + 2 * i;
        int k1 = k0 + 1;
        if (k0 >= 81) break;   // tail words permanently zero (pre-zeroed)
        float v0 = ys[(k0 / 9) * 20 + (k0 % 9)];
        float v1 = (k1 < 81) ? ys[(k1 / 9) * 20 + (k1 % 9)] : 0.f;
        __nv_bfloat162 h = __floats2bfloat162_rn(v0, v1);
        dst[i] = *(uint32_t*)&h;
    }
}

__global__ void __launch_bounds__(256, 2) conv2_mma_kernel(
        const float* __restrict__ pb) {
    extern __shared__ float sm[];
    uint32_t* bSm = (uint32_t*)sm;            // 2 x 7488 words
    float*    ySm = sm + 2 * C2_BW;           // 2 x 1600 floats

    uint32_t bAddr = smem_u32(bSm);
    uint32_t yAddr = smem_u32(ySm);

    int t = threadIdx.x, lane = t & 31, wid = t >> 5;
    int gid = lane >> 2, tig = lane & 3;
    int wm = wid >> 1, wn = wid & 1;
    int half = blockIdx.x;
    int b0 = blockIdx.y * 4;

    // zero both B buffers once (tail words stay zero forever)
    for (int i = t; i < 2 * C2_BW; i += 256) bSm[i] = 0u;

    // build geometry (ic-invariant): 432 units = 144 n x 3 k-groups;
    // thread owns units t and t+256 (second active for t<176).
    int gkg[2], gyofs[2], gdst[2];
    bool gact[2];
#pragma unroll
    for (int s = 0; s < 2; s++) {
        int u = t + s * 256;
        gact[s] = (u < 432);
        int uu = gact[s] ? u : 0;
        int n = uu % 144, kg = uu / 144;
        int img = n / 36, pix = n % 36;
        int oh = pix / 6, ow = pix - oh * 6;
        gkg[s] = kg;
        gyofs[s] = img * 400 + 40 * oh + 2 * ow;
        gdst[s] = n * 52 + kg * 16;
    }

    // ldmatrix lane offset for B (bytes within one B buffer)
    int l8 = lane & 7, lHi = (lane >> 3) & 1;
    uint32_t bLaneOff = (uint32_t)(((wn * 72 + l8) * 52 + lHi * 4) * 4);

    // A fragment base (gmem, L2-resident)
    const uint32_t* aBase = g_wbf + (size_t)half * 256 * 6656
                          + (wm * 32 + gid) * 52 + tig;

    float acc[2][9][4];
#pragma unroll
    for (int mt = 0; mt < 2; mt++)
#pragma unroll
        for (int j = 0; j < 9; j++)
#pragma unroll
            for (int k = 0; k < 4; k++) acc[mt][j][k] = 0.f;

    // ---- prologue: y(0) -> buf0, y(1) -> buf1 ----
    for (int i = t; i < 1024; i += 256) {
        int buf = i >> 9, r = i & 511;
        int im = r >> 7, off = r & 127;
        if (off < 100)
            cp16(yAddr + (buf * C2_YW + im * 400 + off * 4) * 4,
                 g_y + ((size_t)(b0 + im) * 256 + buf) * 400 + off * 4);
    }
    CP_COMMIT();
    CP_WAIT0();
    __syncthreads();
    // build B(0) into b[0]
#pragma unroll
    for (int s = 0; s < 2; s++) {
        if (gact[s]) {
            uint32_t* dst = bSm + gdst[s];
            const float* ys = ySm + gyofs[s];
            if (gkg[s] == 0)      emit_b<0>(dst, ys);
            else if (gkg[s] == 1) emit_b<1>(dst, ys);
            else                  emit_b<2>(dst, ys);
        }
    }

    for (int ic = 0; ic < 256; ic++) {
        CP_WAIT0();        // y(ic+1) resident
        __syncthreads();   // B(ic) built; mma(ic-1) done; y[ic&1] readers done

        // prefetch y(ic+2) -> y[ic&1]
        if (ic + 2 < 256) {
            for (int i = t; i < 512; i += 256) {
                int im = i >> 7, off = i & 127;
                if (off < 100)
                    cp16(yAddr + ((ic & 1) * C2_YW + im * 400 + off * 4) * 4,
                         g_y + ((size_t)(b0 + im) * 256 + (ic + 2)) * 400 + off * 4);
            }
        }
        CP_COMMIT();

        // preload A fragments for s=0
        const uint32_t* aIC = aBase + (size_t)ic * 6656;
        uint32_t areg[2][2][4];
#pragma unroll
        for (int mt = 0; mt < 2; mt++) {
            const uint32_t* ap = aIC + mt * 832;
            areg[0][mt][0] = ap[0];
            areg[0][mt][1] = ap[416];
            areg[0][mt][2] = ap[4];
            areg[0][mt][3] = ap[420];
        }

        // build B(ic+1) into b[(ic+1)&1] (overlaps mma below)
        if (ic + 1 < 256) {
            uint32_t* bNext = bSm + ((ic + 1) & 1) * C2_BW;
            const float* yNext = ySm + ((ic + 1) & 1) * C2_YW;
#pragma unroll
            for (int s = 0; s < 2; s++) {
                if (gact[s]) {
                    uint32_t* dst = bNext + gdst[s];
                    const float* ys = yNext + gyofs[s];
                    if (gkg[s] == 0)      emit_b<0>(dst, ys);
                    else if (gkg[s] == 1) emit_b<1>(dst, ys);
                    else                  emit_b<2>(dst, ys);
                }
            }
        }

        // mma(ic): A from gmem regs, B via ldmatrix from b[ic&1]
        uint32_t bIter = bAddr + (ic & 1) * (C2_BW * 4) + bLaneOff;
#pragma unroll
        for (int s = 0; s < 6; s++) {
            int cb = s & 1;
            if (s < 5) {
#pragma unroll
                for (int mt = 0; mt < 2; mt++) {
                    const uint32_t* ap = aIC + mt * 832 + (s + 1) * 8;
                    areg[cb ^ 1][mt][0] = ap[0];
                    areg[cb ^ 1][mt][1] = ap[416];
                    areg[cb ^ 1][mt][2] = ap[4];
                    areg[cb ^ 1][mt][3] = ap[420];
                }
            }
#pragma unroll
            for (int j = 0; j < 9; j++) {
                uint32_t baddr = bIter + j * (8 * 52 * 4) + s * 32;
                uint32_t br0, br1;
                asm volatile(
                    "ldmatrix.sync.aligned.m8n8.x2.shared.b16 {%0,%1}, [%2];"
                    : "=r"(br0), "=r"(br1) : "r"(baddr));
#pragma unroll
                for (int mt = 0; mt < 2; mt++) {
                    asm volatile(
                        "mma.sync.aligned.m16n8k16.row.col.f32.bf16.bf16.f32 "
                        "{%0,%1,%2,%3},{%4,%5,%6,%7},{%8,%9},{%0,%1,%2,%3};"
                        : "+f"(acc[mt][j][0]), "+f"(acc[mt][j][1]),
                          "+f"(acc[mt][j][2]), "+f"(acc[mt][j][3])
                        : "r"(areg[cb][mt][0]), "r"(areg[cb][mt][1]),
                          "r"(areg[cb][mt][2]), "r"(areg[cb][mt][3]),
                          "r"(br0), "r"(br1));
                }
            }
        }
    }

    // epilogue: D[oc][n] -> g_u[b][r][i] + bias
    int ocb = half * 128;
#pragma unroll
    for (int mt = 0; mt < 2; mt++) {
        int row0 = wm * 32 + mt * 16 + gid;
#pragma unroll
        for (int h2 = 0; h2 < 2; h2++) {
            int oc = ocb + row0 + h2 * 8;
            float bv = pb[oc];
            int i8 = oc >> 5, m = oc & 31;
#pragma unroll
            for (int j = 0; j < 9; j++) {
#pragma unroll
                for (int cc = 0; cc < 2; cc++) {
                    int n = wn * 72 + j * 8 + 2 * tig + cc;
                    int img = n / 36, pix = n - 36 * img;
                    g_u[((size_t)(b0 + img)) * 9216 + (m * 36 + pix) * 8 + i8] =
                        acc[mt][j][h2 * 2 + cc] + bv;
                }
            }
        }
    }
}

// ======================================================================
// squash u over the 8-dim capsule axis (in place)
// ======================================================================
__global__ void squash_kernel() {
    int idx = blockIdx.x * blockDim.x + threadIdx.x;
    if (idx >= NB * 1152) return;
    float* p = g_u + (size_t)idx * 8;
    float4 a = *(float4*)p, b = *(float4*)(p + 4);
    float sn = a.x*a.x + a.y*a.y + a.z*a.z + a.w*a.w
             + b.x*b.x + b.y*b.y + b.z*b.z + b.w*b.w;
    float sc = sqrtf(sn) / (1.f + sn);
    a.x *= sc; a.y *= sc; a.z *= sc; a.w *= sc;
    b.x *= sc; b.y *= sc; b.z *= sc; b.w *= sc;
    *(float4*)p = a; *(float4*)(p + 4) = b;
}

// ======================================================================
// Fused priors + 3 routing iterations. Block = (c, b), 512 threads.
// ======================================================================
__global__ void __launch_bounds__(512, 2) route_kernel(const float* __restrict__ rw) {
    extern __shared__ float sm2[];
    float* spri  = sm2;               // 18432
    float* sblog = sm2 + 18432;       // 1152
    float* sred  = sblog + 1152;      // 256
    float* sv    = sred + 256;        // 16
    float* sscr  = sv + 16;           // 40
    int c = blockIdx.x, b = blockIdx.y, t = threadIdx.x;
    int lane = t & 31, warp = t >> 5;   // 16 warps

    for (int r = t; r < 1152; r += 512) sblog[r] = 0.f;

    {
        int o4 = (t & 3) * 4, rb = t >> 2;
        const float* ub = g_u + (size_t)b * 9216;
        for (int j = 0; j < 9; j++) {
            int r = rb + 128 * j;
            const float* wr = rw + ((size_t)c * 1152 + r) * 128 + o4;
            const float4* ur = (const float4*)(ub + r * 8);
            float4 u0 = ur[0], u1 = ur[1];
            float uu[8] = {u0.x, u0.y, u0.z, u0.w, u1.x, u1.y, u1.z, u1.w};
            float ax = 0.f, ay = 0.f, az = 0.f, aw = 0.f;
#pragma unroll
            for (int i = 0; i < 8; i++) {
                float uv = uu[i];
                float4 w = *(const float4*)(wr + i * 16);
                ax += uv * w.x; ay += uv * w.y; az += uv * w.z; aw += uv * w.w;
            }
            float4 o; o.x = ax; o.y = ay; o.z = az; o.w = aw;
            *(float4*)(spri + r * 16 + o4) = o;
        }
    }
    __syncthreads();

    float snv = 0.f;
    for (int iter = 0; iter < 3; iter++) {
        float lm = -1e30f;
        for (int r = t; r < 1152; r += 512) lm = fmaxf(lm, sblog[r]);
#pragma unroll
        for (int off = 16; off; off >>= 1)
            lm = fmaxf(lm, __shfl_xor_sync(0xffffffffu, lm, off));
        if (lane == 0) sscr[warp] = lm;
        __syncthreads();
        float bmax = sscr[0];
#pragma unroll
        for (int wn = 1; wn < 16; wn++) bmax = fmaxf(bmax, sscr[wn]);
        float ls = 0.f;
        for (int r = t; r < 1152; r += 512) ls += expf(sblog[r] - bmax);
#pragma unroll
        for (int off = 16; off; off >>= 1)
            ls += __shfl_xor_sync(0xffffffffu, ls, off);
        if (lane == 0) sscr[16 + warp] = ls;
        __syncthreads();
        float bsum = 0.f;
#pragma unroll
        for (int wn = 0; wn < 16; wn++) bsum += sscr[16 + wn];
        float inv = 1.f / bsum;

        float sa[16];
#pragma unroll
        for (int o = 0; o < 16; o++) sa[o] = 0.f;
        for (int r = t; r < 1152; r += 512) {
            float pr = expf(sblog[r] - bmax) * inv;
            const float* pp = spri + r * 16;
#pragma unroll
            for (int o = 0; o < 16; o++) sa[o] += pp[o] * pr;
        }
#pragma unroll
        for (int o = 0; o < 16; o++) {
#pragma unroll
            for (int off = 16; off; off >>= 1)
                sa[o] += __shfl_xor_sync(0xffffffffu, sa[o], off);
        }
        if (lane == 0) {
#pragma unroll
            for (int o = 0; o < 16; o++) sred[warp * 16 + o] = sa[o];
        }
        __syncthreads();
        if (t < 32) {
            float sval = 0.f;
            if (t < 16) {
#pragma unroll
                for (int wn = 0; wn < 16; wn++) sval += sred[wn * 16 + t];
            }
            float sn = sval * sval;
#pragma unroll
            for (int off = 16; off; off >>= 1)
                sn += __shfl_xor_sync(0xffffffffu, sn, off);
            float sc = sqrtf(sn) / (1.f + sn);
            if (t < 16) sv[t] = sval * sc;
            if (t == 0) sscr[32] = sn;
        }
        __syncthreads();
        snv = sscr[32];

        if (iter < 2) {
            for (int r = t; r < 1152; r += 512) {
                const float* pp = spri + r * 16;
                float d = 0.f;
#pragma unroll
                for (int o = 0; o < 16; o++) d += pp[o] * sv[o];
                sblog[r] += d;
            }
            __syncthreads();
        }
    }
    if (t == 0) g_logits[b * 10 + c] = snv / (1.f + snv);
}

// ======================================================================
__global__ void softmax_kernel(float* __restrict__ out) {
    int b = blockIdx.x * blockDim.x + threadIdx.x;
    if (b >= NB) return;
    float l[10];
#pragma unroll
    for (int i = 0; i < 10; i++) l[i] = g_logits[b * 10 + i];
    float m = l[0];
#pragma unroll
    for (int i = 1; i < 10; i++) m = fmaxf(m, l[i]);
    float s = 0.f;
#pragma unroll
    for (int i = 0; i < 10; i++) { l[i] = expf(l[i] - m); s += l[i]; }
    float inv = 1.f / s;
#pragma unroll
    for (int i = 0; i < 10; i++) out[b * 10 + i] = l[i] * inv;
}

// ======================================================================
extern "C" void kernel_launch(void* const* d_in, const int* in_sizes, int n_in,
                              void* d_out, int out_size) {
    const float* x  = (const float*)d_in[0];
    const float* cw = (const float*)d_in[1];
    const float* cb = (const float*)d_in[2];
    const float* pw = (const float*)d_in[3];
    const float* pb = (const float*)d_in[4];
    const float* rw = (const float*)d_in[5];
    float* out = (float*)d_out;

    const int c1_smem = (20736 + 252) * 4;
    const int rt_smem = (18432 + 1152 + 256 + 16 + 40) * 4;
    cudaFuncSetAttribute(conv1_kernel,
        cudaFuncAttributeMaxDynamicSharedMemorySize, c1_smem);
    cudaFuncSetAttribute(conv2_mma_kernel,
        cudaFuncAttributeMaxDynamicSharedMemorySize, C2_SMEM);
    cudaFuncSetAttribute(route_kernel,
        cudaFuncAttributeMaxDynamicSharedMemorySize, rt_smem);

    prep_w_kernel<<<(int)(((size_t)2 * 256 * 128 * 52 + 255) / 256), 256>>>(pw);
    conv1_kernel<<<dim3(20, NB), 256, c1_smem>>>(x, cw, cb);
    conv2_mma_kernel<<<dim3(2, NB / 4), 256, C2_SMEM>>>(pb);
    squash_kernel<<<(NB * 1152 + 255) / 256, 256>>>();
    route_kernel<<<dim3(10, NB), 512, rt_smem>>>(rw);
    softmax_kernel<<<(NB + 255) / 256, 256>>>(out);
}

// round 9
// speedup vs baseline: 1.1911x; 1.0038x over previous
#include <cuda_runtime.h>
#include <cuda_bf16.h>
#include <math.h>
#include <cstdint>

// ---------------- problem constants ----------------
// x:      [512, 1, 28, 28]
// conv_w: [256, 1, 9, 9]   conv_b: [256]
// y:      [512, 256, 20, 20]
// prim_w: [256 oc][256 ic][9][9], stride 2 -> p: [512, 256, 6, 6]
// u:      [512, 1152, 8]   (r = m*36 + oh*6 + ow, i = oc>>5, m = oc&31)
// route_w:[10, 1152, 8, 16]
// out:    [512, 10]

#define NB 512

// ---------------- scratch ----------------
__device__ float    g_y[(size_t)NB * 256 * 400];        // 210 MB
__device__ float    g_u[(size_t)NB * 1152 * 8];         // 18.9 MB
__device__ uint32_t g_wbf[(size_t)2 * 256 * 128 * 52];  // 13.1 MB [half][ic][ocl][52 bf16x2]
__device__ float    g_logits[NB * 10];

// ---------------- PTX helpers (generic, sm_80+) ----------------
__device__ __forceinline__ uint32_t smem_u32(const void* p) {
    uint32_t a;
    asm("{ .reg .u64 t; cvta.to.shared.u64 t, %1; cvt.u32.u64 %0, t; }"
        : "=r"(a) : "l"(p));
    return a;
}
__device__ __forceinline__ void cp16(uint32_t dst, const void* src) {
    asm volatile("cp.async.ca.shared.global [%0], [%1], 16;"
                 :: "r"(dst), "l"(src) : "memory");
}
#define CP_COMMIT() asm volatile("cp.async.commit_group;" ::: "memory")
#define CP_WAIT0()  asm volatile("cp.async.wait_group 0;" ::: "memory")

// ======================================================================
// weight prep: prim_w -> bf16x2 pairs, taps 81..103 zero
// ======================================================================
__global__ void prep_w_kernel(const float* __restrict__ pw) {
    size_t idx = (size_t)blockIdx.x * 256 + threadIdx.x;
    const size_t total = (size_t)2 * 256 * 128 * 52;
    if (idx >= total) return;
    int p = (int)(idx % 52);
    size_t r = idx / 52;
    int ocl = (int)(r % 128);
    size_t r2 = r / 128;
    int ic = (int)(r2 % 256);
    int half = (int)(r2 / 256);
    int k0 = 2 * p, k1 = 2 * p + 1;
    const float* src = pw + ((size_t)(half * 128 + ocl)) * 20736 + ic * 81;
    float v0 = (k0 < 81) ? src[k0] : 0.f;
    float v1 = (k1 < 81) ? src[k1] : 0.f;
    __nv_bfloat162 h = __floats2bfloat162_rn(v0, v1);
    g_wbf[idx] = *(uint32_t*)&h;
}

// ======================================================================
// conv1: block = (oh, b), 256 threads = oc
// ======================================================================
__global__ void conv1_kernel(const float* __restrict__ x,
                             const float* __restrict__ w,
                             const float* __restrict__ bias) {
    extern __shared__ float sm1[];
    float* sw = sm1;
    float* sx = sm1 + 20736;
    int oh = blockIdx.x, b = blockIdx.y, t = threadIdx.x;

    for (int i = t; i < 20736; i += 256) sw[i] = w[i];
    if (t < 252) sx[t] = x[(size_t)b * 784 + oh * 28 + t];
    __syncthreads();

    int oc = t;
    float acc[20];
    float bv = bias[oc];
#pragma unroll
    for (int i = 0; i < 20; i++) acc[i] = bv;

    const float* wp = sw + oc * 81;
#pragma unroll
    for (int kh = 0; kh < 9; kh++) {
        float rin[28];
#pragma unroll
        for (int j = 0; j < 28; j++) rin[j] = sx[kh * 28 + j];
#pragma unroll
        for (int kw = 0; kw < 9; kw++) {
            float wv = wp[kh * 9 + kw];
#pragma unroll
            for (int ow = 0; ow < 20; ow++) acc[ow] += wv * rin[kw + ow];
        }
    }
    float* yp = g_y + ((size_t)(b * 256 + oc)) * 400 + oh * 20;
#pragma unroll
    for (int ow = 0; ow < 20; ow++) yp[ow] = acc[ow];
}

// ======================================================================
// conv2 via mma.sync bf16 m16n8k16.
//   Block: 128 oc x 144 px (4 images, exact). 256 thr = 4(M) x 2(N) warps.
//   Warp tile 32 oc x 72 px (j=9). K = 256 ic x 96 words (81 real).
//   A: register fragments loaded DIRECTLY from g_wbf (L2), no smem.
//   B: double-buffered smem [2][144][52]w, built from y; build(ic+1)
//      overlaps mma(ic) -> ONE barrier per ic.
//   B frags via ldmatrix.x2 (row stride 52 words = conflict-free).
//   y: double-buffered via cp.async, distance 2.
//   smem: 2*7488w + 2*1600w = 72,704 B.
// ======================================================================
#define C2_BW 7488
#define C2_YW 1600
#define C2_SMEM ((2 * C2_BW + 2 * C2_YW) * 4)

template <int KG>
__device__ __forceinline__ void emit_b(uint32_t* dst, const float* ys) {
#pragma unroll
    for (int i = 0; i < 16; i++) {
        int k0 = 32 * KG + 2 * i;
        int k1 = k0 + 1;
        if (k0 >= 81) break;   // tail words permanently zero (pre-zeroed)
        float v0 = ys[(k0 / 9) * 20 + (k0 % 9)];
        float v1 = (k1 < 81) ? ys[(k1 / 9) * 20 + (k1 % 9)] : 0.f;
        __nv_bfloat162 h = __floats2bfloat162_rn(v0, v1);
        dst[i] = *(uint32_t*)&h;
    }
}

__global__ void __launch_bounds__(256, 2) conv2_mma_kernel(
        const float* __restrict__ pb) {
    extern __shared__ float sm[];
    uint32_t* bSm = (uint32_t*)sm;            // 2 x 7488 words
    float*    ySm = sm + 2 * C2_BW;           // 2 x 1600 floats

    uint32_t bAddr = smem_u32(bSm);
    uint32_t yAddr = smem_u32(ySm);

    int t = threadIdx.x, lane = t & 31, wid = t >> 5;
    int gid = lane >> 2, tig = lane & 3;
    int wm = wid >> 1, wn = wid & 1;
    int half = blockIdx.x;
    int b0 = blockIdx.y * 4;

    // zero both B buffers once (tail words stay zero forever)
    for (int i = t; i < 2 * C2_BW; i += 256) bSm[i] = 0u;

    // build geometry (ic-invariant): 432 units = 144 n x 3 k-groups;
    // thread owns units t and t+256 (second active for t<176).
    int gkg[2], gyofs[2], gdst[2];
    bool gact[2];
#pragma unroll
    for (int s = 0; s < 2; s++) {
        int u = t + s * 256;
        gact[s] = (u < 432);
        int uu = gact[s] ? u : 0;
        int n = uu % 144, kg = uu / 144;
        int img = n / 36, pix = n % 36;
        int oh = pix / 6, ow = pix - oh * 6;
        gkg[s] = kg;
        gyofs[s] = img * 400 + 40 * oh + 2 * ow;
        gdst[s] = n * 52 + kg * 16;
    }

    // ldmatrix lane offset for B (bytes within one B buffer)
    int l8 = lane & 7, lHi = (lane >> 3) & 1;
    uint32_t bLaneOff = (uint32_t)(((wn * 72 + l8) * 52 + lHi * 4) * 4);

    // A fragment base (gmem, L2-resident)
    const uint32_t* aBase = g_wbf + (size_t)half * 256 * 6656
                          + (wm * 32 + gid) * 52 + tig;

    float acc[2][9][4];
#pragma unroll
    for (int mt = 0; mt < 2; mt++)
#pragma unroll
        for (int j = 0; j < 9; j++)
#pragma unroll
            for (int k = 0; k < 4; k++) acc[mt][j][k] = 0.f;

    // ---- prologue: y(0) -> buf0, y(1) -> buf1 ----
    for (int i = t; i < 1024; i += 256) {
        int buf = i >> 9, r = i & 511;
        int im = r >> 7, off = r & 127;
        if (off < 100)
            cp16(yAddr + (buf * C2_YW + im * 400 + off * 4) * 4,
                 g_y + ((size_t)(b0 + im) * 256 + buf) * 400 + off * 4);
    }
    CP_COMMIT();
    CP_WAIT0();
    __syncthreads();
    // build B(0) into b[0]
#pragma unroll
    for (int s = 0; s < 2; s++) {
        if (gact[s]) {
            uint32_t* dst = bSm + gdst[s];
            const float* ys = ySm + gyofs[s];
            if (gkg[s] == 0)      emit_b<0>(dst, ys);
            else if (gkg[s] == 1) emit_b<1>(dst, ys);
            else                  emit_b<2>(dst, ys);
        }
    }

    for (int ic = 0; ic < 256; ic++) {
        CP_WAIT0();        // y(ic+1) resident
        __syncthreads();   // B(ic) built; mma(ic-1) done; y[ic&1] readers done

        // prefetch y(ic+2) -> y[ic&1]
        if (ic + 2 < 256) {
            for (int i = t; i < 512; i += 256) {
                int im = i >> 7, off = i & 127;
                if (off < 100)
                    cp16(yAddr + ((ic & 1) * C2_YW + im * 400 + off * 4) * 4,
                         g_y + ((size_t)(b0 + im) * 256 + (ic + 2)) * 400 + off * 4);
            }
        }
        CP_COMMIT();

        // preload A fragments for s=0
        const uint32_t* aIC = aBase + (size_t)ic * 6656;
        uint32_t areg[2][2][4];
#pragma unroll
        for (int mt = 0; mt < 2; mt++) {
            const uint32_t* ap = aIC + mt * 832;
            areg[0][mt][0] = ap[0];
            areg[0][mt][1] = ap[416];
            areg[0][mt][2] = ap[4];
            areg[0][mt][3] = ap[420];
        }

        // build B(ic+1) into b[(ic+1)&1] (overlaps mma below)
        if (ic + 1 < 256) {
            uint32_t* bNext = bSm + ((ic + 1) & 1) * C2_BW;
            const float* yNext = ySm + ((ic + 1) & 1) * C2_YW;
#pragma unroll
            for (int s = 0; s < 2; s++) {
                if (gact[s]) {
                    uint32_t* dst = bNext + gdst[s];
                    const float* ys = yNext + gyofs[s];
                    if (gkg[s] == 0)      emit_b<0>(dst, ys);
                    else if (gkg[s] == 1) emit_b<1>(dst, ys);
                    else                  emit_b<2>(dst, ys);
                }
            }
        }

        // mma(ic): A from gmem regs, B via ldmatrix from b[ic&1]
        uint32_t bIter = bAddr + (ic & 1) * (C2_BW * 4) + bLaneOff;
#pragma unroll
        for (int s = 0; s < 6; s++) {
            int cb = s & 1;
            if (s < 5) {
#pragma unroll
                for (int mt = 0; mt < 2; mt++) {
                    const uint32_t* ap = aIC + mt * 832 + (s + 1) * 8;
                    areg[cb ^ 1][mt][0] = ap[0];
                    areg[cb ^ 1][mt][1] = ap[416];
                    areg[cb ^ 1][mt][2] = ap[4];
                    areg[cb ^ 1][mt][3] = ap[420];
                }
            }
#pragma unroll
            for (int j = 0; j < 9; j++) {
                uint32_t baddr = bIter + j * (8 * 52 * 4) + s * 32;
                uint32_t br0, br1;
                asm volatile(
                    "ldmatrix.sync.aligned.m8n8.x2.shared.b16 {%0,%1}, [%2];"
                    : "=r"(br0), "=r"(br1) : "r"(baddr));
#pragma unroll
                for (int mt = 0; mt < 2; mt++) {
                    asm volatile(
                        "mma.sync.aligned.m16n8k16.row.col.f32.bf16.bf16.f32 "
                        "{%0,%1,%2,%3},{%4,%5,%6,%7},{%8,%9},{%0,%1,%2,%3};"
                        : "+f"(acc[mt][j][0]), "+f"(acc[mt][j][1]),
                          "+f"(acc[mt][j][2]), "+f"(acc[mt][j][3])
                        : "r"(areg[cb][mt][0]), "r"(areg[cb][mt][1]),
                          "r"(areg[cb][mt][2]), "r"(areg[cb][mt][3]),
                          "r"(br0), "r"(br1));
                }
            }
        }
    }

    // epilogue: D[oc][n] -> g_u[b][r][i] + bias
    int ocb = half * 128;
#pragma unroll
    for (int mt = 0; mt < 2; mt++) {
        int row0 = wm * 32 + mt * 16 + gid;
#pragma unroll
        for (int h2 = 0; h2 < 2; h2++) {
            int oc = ocb + row0 + h2 * 8;
            float bv = pb[oc];
            int i8 = oc >> 5, m = oc & 31;
#pragma unroll
            for (int j = 0; j < 9; j++) {
#pragma unroll
                for (int cc = 0; cc < 2; cc++) {
                    int n = wn * 72 + j * 8 + 2 * tig + cc;
                    int img = n / 36, pix = n - 36 * img;
                    g_u[((size_t)(b0 + img)) * 9216 + (m * 36 + pix) * 8 + i8] =
                        acc[mt][j][h2 * 2 + cc] + bv;
                }
            }
        }
    }
}

// ======================================================================
// squash u over the 8-dim capsule axis (in place)
// ======================================================================
__global__ void squash_kernel() {
    int idx = blockIdx.x * blockDim.x + threadIdx.x;
    if (idx >= NB * 1152) return;
    float* p = g_u + (size_t)idx * 8;
    float4 a = *(float4*)p, b = *(float4*)(p + 4);
    float sn = a.x*a.x + a.y*a.y + a.z*a.z + a.w*a.w
             + b.x*b.x + b.y*b.y + b.z*b.z + b.w*b.w;
    float sc = sqrtf(sn) / (1.f + sn);
    a.x *= sc; a.y *= sc; a.z *= sc; a.w *= sc;
    b.x *= sc; b.y *= sc; b.z *= sc; b.w *= sc;
    *(float4*)p = a; *(float4*)(p + 4) = b;
}

// ======================================================================
// Fused priors + 3 routing iterations. Block = (c, b), 512 threads.
// ======================================================================
__global__ void __launch_bounds__(512, 2) route_kernel(const float* __restrict__ rw) {
    extern __shared__ float sm2[];
    float* spri  = sm2;               // 18432
    float* sblog = sm2 + 18432;       // 1152
    float* sred  = sblog + 1152;      // 256
    float* sv    = sred + 256;        // 16
    float* sscr  = sv + 16;           // 40
    int c = blockIdx.x, b = blockIdx.y, t = threadIdx.x;
    int lane = t & 31, warp = t >> 5;   // 16 warps

    for (int r = t; r < 1152; r += 512) sblog[r] = 0.f;

    {
        int o4 = (t & 3) * 4, rb = t >> 2;
        const float* ub = g_u + (size_t)b * 9216;
        for (int j = 0; j < 9; j++) {
            int r = rb + 128 * j;
            const float* wr = rw + ((size_t)c * 1152 + r) * 128 + o4;
            const float4* ur = (const float4*)(ub + r * 8);
            float4 u0 = ur[0], u1 = ur[1];
            float uu[8] = {u0.x, u0.y, u0.z, u0.w, u1.x, u1.y, u1.z, u1.w};
            float ax = 0.f, ay = 0.f, az = 0.f, aw = 0.f;
#pragma unroll
            for (int i = 0; i < 8; i++) {
                float uv = uu[i];
                float4 w = *(const float4*)(wr + i * 16);
                ax += uv * w.x; ay += uv * w.y; az += uv * w.z; aw += uv * w.w;
            }
            float4 o; o.x = ax; o.y = ay; o.z = az; o.w = aw;
            *(float4*)(spri + r * 16 + o4) = o;
        }
    }
    __syncthreads();

    float snv = 0.f;
    for (int iter = 0; iter < 3; iter++) {
        float lm = -1e30f;
        for (int r = t; r < 1152; r += 512) lm = fmaxf(lm, sblog[r]);
#pragma unroll
        for (int off = 16; off; off >>= 1)
            lm = fmaxf(lm, __shfl_xor_sync(0xffffffffu, lm, off));
        if (lane == 0) sscr[warp] = lm;
        __syncthreads();
        float bmax = sscr[0];
#pragma unroll
        for (int wn = 1; wn < 16; wn++) bmax = fmaxf(bmax, sscr[wn]);
        float ls = 0.f;
        for (int r = t; r < 1152; r += 512) ls += expf(sblog[r] - bmax);
#pragma unroll
        for (int off = 16; off; off >>= 1)
            ls += __shfl_xor_sync(0xffffffffu, ls, off);
        if (lane == 0) sscr[16 + warp] = ls;
        __syncthreads();
        float bsum = 0.f;
#pragma unroll
        for (int wn = 0; wn < 16; wn++) bsum += sscr[16 + wn];
        float inv = 1.f / bsum;

        float sa[16];
#pragma unroll
        for (int o = 0; o < 16; o++) sa[o] = 0.f;
        for (int r = t; r < 1152; r += 512) {
            float pr = expf(sblog[r] - bmax) * inv;
            const float* pp = spri + r * 16;
#pragma unroll
            for (int o = 0; o < 16; o++) sa[o] += pp[o] * pr;
        }
#pragma unroll
        for (int o = 0; o < 16; o++) {
#pragma unroll
            for (int off = 16; off; off >>= 1)
                sa[o] += __shfl_xor_sync(0xffffffffu, sa[o], off);
        }
        if (lane == 0) {
#pragma unroll
            for (int o = 0; o < 16; o++) sred[warp * 16 + o] = sa[o];
        }
        __syncthreads();
        if (t < 32) {
            float sval = 0.f;
            if (t < 16) {
#pragma unroll
                for (int wn = 0; wn < 16; wn++) sval += sred[wn * 16 + t];
            }
            float sn = sval * sval;
#pragma unroll
            for (int off = 16; off; off >>= 1)
                sn += __shfl_xor_sync(0xffffffffu, sn, off);
            float sc = sqrtf(sn) / (1.f + sn);
            if (t < 16) sv[t] = sval * sc;
            if (t == 0) sscr[32] = sn;
        }
        __syncthreads();
        snv = sscr[32];

        if (iter < 2) {
            for (int r = t; r < 1152; r += 512) {
                const float* pp = spri + r * 16;
                float d = 0.f;
#pragma unroll
                for (int o = 0; o < 16; o++) d += pp[o] * sv[o];
                sblog[r] += d;
            }
            __syncthreads();
        }
    }
    if (t == 0) g_logits[b * 10 + c] = snv / (1.f + snv);
}

// ======================================================================
__global__ void softmax_kernel(float* __restrict__ out) {
    int b = blockIdx.x * blockDim.x + threadIdx.x;
    if (b >= NB) return;
    float l[10];
#pragma unroll
    for (int i = 0; i < 10; i++) l[i] = g_logits[b * 10 + i];
    float m = l[0];
#pragma unroll
    for (int i = 1; i < 10; i++) m = fmaxf(m, l[i]);
    float s = 0.f;
#pragma unroll
    for (int i = 0; i < 10; i++) { l[i] = expf(l[i] - m); s += l[i]; }
    float inv = 1.f / s;
#pragma unroll
    for (int i = 0; i < 10; i++) out[b * 10 + i] = l[i] * inv;
}

// ======================================================================
extern "C" void kernel_launch(void* const* d_in, const int* in_sizes, int n_in,
                              void* d_out, int out_size) {
    const float* x  = (const float*)d_in[0];
    const float* cw = (const float*)d_in[1];
    const float* cb = (const float*)d_in[2];
    const float* pw = (const float*)d_in[3];
    const float* pb = (const float*)d_in[4];
    const float* rw = (const float*)d_in[5];
    float* out = (float*)d_out;

    const int c1_smem = (20736 + 252) * 4;
    const int rt_smem = (18432 + 1152 + 256 + 16 + 40) * 4;
    cudaFuncSetAttribute(conv1_kernel,
        cudaFuncAttributeMaxDynamicSharedMemorySize, c1_smem);
    cudaFuncSetAttribute(conv2_mma_kernel,
        cudaFuncAttributeMaxDynamicSharedMemorySize, C2_SMEM);
    cudaFuncSetAttribute(route_kernel,
        cudaFuncAttributeMaxDynamicSharedMemorySize, rt_smem);

    prep_w_kernel<<<(int)(((size_t)2 * 256 * 128 * 52 + 255) / 256), 256>>>(pw);
    conv1_kernel<<<dim3(20, NB), 256, c1_smem>>>(x, cw, cb);
    conv2_mma_kernel<<<dim3(2, NB / 4), 256, C2_SMEM>>>(pb);
    squash_kernel<<<(NB * 1152 + 255) / 256, 256>>>();
    route_kernel<<<dim3(10, NB), 512, rt_smem>>>(rw);
    softmax_kernel<<<(NB + 255) / 256, 256>>>(out);
}